// round 10
// baseline (speedup 1.0000x reference)
#include <cuda_runtime.h>
#include <cstdint>

// PSROIPool (R-FCN / caffe semantics) — pipelined plane streaming.
//
// 784 blocks; each block owns 4 feature planes sharing the same
// (batch b, bin position pos = ph*7+pw), i.e. planes c = (q*4+i)*49 + pos.
// Per block: compute ROI bin bounds ONCE (they depend only on r and pos),
// then stream the 4 planes through a double-buffered cp.async pipeline,
// gathering each ROI's rect sum from SMEM while the next plane loads.
//
// features: [N=4, C=784, H=96, W=96] fp32
// rois:     [R=1024, 5] fp32 = (batch_idx, x1, y1, x2, y2)
// out:      [R, D=16, PH=7, PW=7] fp32 ; out[r*784 + c]
//
// Boundary math replicates the reference FP pipeline:
//   - round() = rintf (round-half-even)
//   - x/7 emulated as x * fl(1/7)   (XLA reciprocal-multiply)
//   - mul and add as SEPARATE correctly-rounded ops (no FMA contraction)

#define GS    7
#define D_    16
#define SCALE 0.0625f
#define C_    (D_ * GS * GS)   // 784
#define H_    96
#define W_    96
#define R_    1024
#define PLANE (H_ * W_)        // 9216 floats = 36 KB
#define NPL   4                // planes per block
#define NTHR  256
#define NBLK  (4 * 49 * 4)     // 784 = batches * positions * quarters

// dynamic smem: buf0[9216] buf1[9216] | rlist[1024] p1[1024] p2[1024]
#define SMEM_BYTES (2 * PLANE * 4 + 3 * R_ * 4)

__device__ __forceinline__ void cp_async16(uint32_t dst, const float4* src) {
    asm volatile("cp.async.cg.shared.global [%0], [%1], 16;\n"
                 :: "r"(dst), "l"(src));
}
__device__ __forceinline__ uint32_t smem_u32(const void* p) {
    return (uint32_t)__cvta_generic_to_shared(p);
}

__global__ __launch_bounds__(NTHR) void psroi_stream_kernel(
    const float* __restrict__ feat,
    const float* __restrict__ rois,
    float* __restrict__ out)
{
    extern __shared__ float smem[];
    float* buf[2] = { smem, smem + PLANE };
    int*   rlist  = (int*)(smem + 2 * PLANE);
    int*   p1     = rlist + R_;   // hs | he<<8 | q0<<16 | nq<<24
    int*   p2     = p1 + R_;      // ws | we<<8 | cnt<<16
    __shared__ int nmatch;

    const int tid = threadIdx.x;
    const int bid = blockIdx.x;
    const int b   = bid / 196;            // batch
    const int rem = bid % 196;
    const int pos = rem / 4;              // ph*7 + pw
    const int qtr = rem % 4;              // d quarter
    const int ph  = pos / GS;
    const int pw  = pos % GS;

    if (tid == 0) nmatch = 0;

    // ---- Kick off prefetch of plane 0 immediately (overlap with bounds) ----
    const size_t plane0 = (size_t)b * C_ + (size_t)(qtr * 4) * 49 + pos;
    {
        const float4* src = reinterpret_cast<const float4*>(feat + plane0 * PLANE);
        uint32_t dst = smem_u32(buf[0]);
        #pragma unroll
        for (int i = 0; i < PLANE / 4 / NTHR; ++i)           // 9
            cp_async16(dst + (tid + i * NTHR) * 16, src + tid + i * NTHR);
        asm volatile("cp.async.commit_group;\n");
    }

    __syncthreads();   // nmatch init visible

    // ---- Per-block ROI bounds (depend only on r and pos) ----
    for (int ri = tid; ri < R_; ri += NTHR) {
        const float* roi = rois + ri * 5;
        if ((int)__ldg(roi) != b) continue;

        float x1 = rintf(__ldg(roi + 1))        * SCALE;
        float y1 = rintf(__ldg(roi + 2))        * SCALE;
        float x2 = rintf(__ldg(roi + 3) + 1.0f) * SCALE;
        float y2 = rintf(__ldg(roi + 4) + 1.0f) * SCALE;

        float roi_w = fmaxf(x2 - x1, 0.1f);
        float roi_h = fmaxf(y2 - y1, 0.1f);

        const float inv7 = 1.0f / 7.0f;     // reciprocal-multiply division
        float bin_h = __fmul_rn(roi_h, inv7);
        float bin_w = __fmul_rn(roi_w, inv7);

        float hs_f = floorf(__fadd_rn(__fmul_rn((float)ph,       bin_h), y1));
        float he_f = ceilf (__fadd_rn(__fmul_rn((float)(ph + 1), bin_h), y1));
        float ws_f = floorf(__fadd_rn(__fmul_rn((float)pw,       bin_w), x1));
        float we_f = ceilf (__fadd_rn(__fmul_rn((float)(pw + 1), bin_w), x1));

        int hs = (int)fminf(fmaxf(hs_f, 0.0f), (float)H_);
        int he = (int)fminf(fmaxf(he_f, 0.0f), (float)H_);
        int ws = (int)fminf(fmaxf(ws_f, 0.0f), (float)W_);
        int we = (int)fminf(fmaxf(we_f, 0.0f), (float)W_);

        int nh = he - hs; if (nh < 0) nh = 0;
        int nw = we - ws; if (nw < 0) nw = 0;
        int cnt = nh * nw;

        int q0 = 0, nq = 0;
        if (cnt > 0) {
            q0 = ws >> 2;
            nq = ((we - 1) >> 2) - q0;
        }

        int p = atomicAdd(&nmatch, 1);
        rlist[p] = ri;
        p1[p] = hs | (he << 8) | (q0 << 16) | (nq << 24);
        p2[p] = ws | (we << 8) | (cnt << 16);
    }

    // ---- Pipelined plane loop ----
    #pragma unroll 1
    for (int i = 0; i < NPL; ++i) {
        // Prefetch next plane into the other buffer.
        if (i + 1 < NPL) {
            const size_t pid = plane0 + (size_t)(i + 1) * 49;
            const float4* src = reinterpret_cast<const float4*>(feat + pid * PLANE);
            uint32_t dst = smem_u32(buf[(i + 1) & 1]);
            #pragma unroll
            for (int k = 0; k < PLANE / 4 / NTHR; ++k)
                cp_async16(dst + (tid + k * NTHR) * 16, src + tid + k * NTHR);
            asm volatile("cp.async.commit_group;\n");
            asm volatile("cp.async.wait_group 1;\n");   // plane i complete
        } else {
            asm volatile("cp.async.wait_group 0;\n");   // last plane complete
        }
        __syncthreads();   // plane i visible to all; bounds visible (iter 0)

        const float* __restrict__ P = buf[i & 1];
        const int c = (qtr * 4 + i) * 49 + pos;
        const int n = nmatch;

        for (int s = tid; s < n; s += NTHR) {
            int w0  = p1[s];
            int w1  = p2[s];
            int hs  =  w0        & 0xFF;
            int he  = (w0 >> 8)  & 0xFF;
            int q0  = (w0 >> 16) & 0xFF;
            int nq  = (w0 >> 24) & 0xFF;
            int ws  =  w1        & 0xFF;
            int we  = (w1 >> 8)  & 0xFF;
            int cnt = (w1 >> 16);

            float result = 0.0f;
            if (cnt > 0) {
                // {0,1} masks over the covering float4 columns.
                float m[3][4];
                #pragma unroll
                for (int j = 0; j < 3; ++j) {
                    #pragma unroll
                    for (int e = 0; e < 4; ++e) {
                        int col = ((q0 + j) << 2) + e;
                        m[j][e] = (j <= nq && col >= ws && col < we) ? 1.0f : 0.0f;
                    }
                }
                float sum = 0.0f;
                #pragma unroll 1
                for (int h = hs; h < he; ++h) {
                    const float4* row4 =
                        reinterpret_cast<const float4*>(P + h * W_) + q0;
                    #pragma unroll
                    for (int j = 0; j < 3; ++j) {
                        float4 v = (j <= nq) ? row4[j]
                                             : make_float4(0.f, 0.f, 0.f, 0.f);
                        sum = fmaf(v.x, m[j][0], sum);
                        sum = fmaf(v.y, m[j][1], sum);
                        sum = fmaf(v.z, m[j][2], sum);
                        sum = fmaf(v.w, m[j][3], sum);
                    }
                }
                result = sum / (float)cnt;
            }
            out[(size_t)rlist[s] * C_ + c] = result;
        }
        __syncthreads();   // buffer i may be overwritten next iteration
    }
}

extern "C" void kernel_launch(void* const* d_in, const int* in_sizes, int n_in,
                              void* d_out, int out_size)
{
    const float* feat = (const float*)d_in[0];
    const float* rois = (const float*)d_in[1];
    float*       out  = (float*)d_out;

    cudaFuncSetAttribute(psroi_stream_kernel,
                         cudaFuncAttributeMaxDynamicSharedMemorySize, SMEM_BYTES);
    psroi_stream_kernel<<<NBLK, NTHR, SMEM_BYTES>>>(feat, rois, out);
}